// round 4
// baseline (speedup 1.0000x reference)
#include <cuda_runtime.h>
#include <cstddef>

// ---------------------------------------------------------------------------
// 2-layer GCN:  out = Norm (Norm (X W1) + b1) W2 + b2, Norm = D^-1/2 (A+I) D^-1/2
// Per layer:
//   s[i]   = dinv[i] * (A_in @ W)[i]
//   agg[d] = s[d] + sum_{edges (s->d)} s[src]
//   h[i]   = dinv[i] * agg[i] + b
//
// Scratch = __device__ globals, referenced ONLY from device code.
// edge_index dtype (int32 vs int64) detected at runtime on device.
// ---------------------------------------------------------------------------

#define NMAX 100000
#define HID 128
#define ODIM 64

__device__ float g_dinv[NMAX];
__device__ float g_s1[(size_t)NMAX * HID];
__device__ float g_agg1[(size_t)NMAX * HID];
__device__ float g_s2[(size_t)NMAX * ODIM];
__device__ float g_agg2[(size_t)NMAX * ODIM];
__device__ int   g_is64;   // 1 if edge_index stored as int64, 0 if int32

// ---- dtype detection -------------------------------------------------------
// If int64 (LE, values in [0,1e5)), words at odd positions are all zero.
// If int32, odd positions hold random edge IDs -> virtually surely nonzero.
__global__ void k_detect(const int* __restrict__ w) {
    __shared__ int any;
    if (threadIdx.x == 0) any = 0;
    __syncthreads();
    // check 2048 odd words
    for (int i = threadIdx.x; i < 2048; i += blockDim.x)
        if (w[2 * i + 1] != 0) { any = 1; }
    __syncthreads();
    if (threadIdx.x == 0) g_is64 = (any == 0) ? 1 : 0;
}

__device__ __forceinline__ int edge_at(const int* __restrict__ w, long long i, int is64) {
    return is64 ? w[2 * i] : w[(int)i];
}

// ---- degree / dinv ---------------------------------------------------------
__global__ void k_fill1(int n) {
    int i = blockIdx.x * blockDim.x + threadIdx.x;
    if (i < n) g_dinv[i] = 1.0f;  // self loop
}

// counts destinations; w = raw edge_index words, dst row starts at word E*(1+is64)
__global__ void k_count(const int* __restrict__ w, int E) {
    int is64 = g_is64;
    const int* dst = w + (size_t)E * (1 + is64);
    int i = blockIdx.x * blockDim.x + threadIdx.x;
    if (i < E) atomicAdd(&g_dinv[edge_at(dst, i, is64)], 1.0f);
}

__global__ void k_rsqrt(int n) {
    int i = blockIdx.x * blockDim.x + threadIdx.x;
    if (i < n) g_dinv[i] = rsqrtf(g_dinv[i]);
}

// ---- GEMM (K=128 fixed), fused input transform + output dinv scale ---------
// Block: 32 rows x NOUT cols, blockDim = NOUT.
// LAYER==1: A = x (param), out -> g_s1/g_agg1, no input transform.
// LAYER==2: A = g_agg1, A_eff[i][k] = dinv[i]*A[i][k] + b1[k] fused, out -> g_s2/g_agg2.
// Writes s = agg = dinv[i] * (A_eff[i] . W[:,f])  (self-loop baked in)
template <int NOUT, int LAYER>
__global__ void __launch_bounds__(NOUT) k_gemm(
    const float* __restrict__ A_in, const float* __restrict__ W,
    const float* __restrict__ bias, int n)
{
    const float* A       = (LAYER == 1) ? A_in : g_agg1;
    float*       s_out   = (LAYER == 1) ? g_s1 : g_s2;
    float*       agg_out = (LAYER == 1) ? g_agg1 : g_agg2;

    __shared__ float As[32 * 64];
    __shared__ float Ws[64 * NOUT];
    const int f = threadIdx.x;
    const int row0 = blockIdx.x * 32;

    float acc[32];
#pragma unroll
    for (int r = 0; r < 32; r++) acc[r] = 0.0f;

    for (int kk = 0; kk < 128; kk += 64) {
        for (int idx = f; idx < 32 * 64; idx += NOUT) {
            int r = idx >> 6, c = idx & 63;
            int row = row0 + r;
            float v = 0.0f;
            if (row < n) {
                v = A[(size_t)row * 128 + kk + c];
                if (LAYER == 2) v = g_dinv[row] * v + bias[kk + c];
            }
            As[idx] = v;
        }
        for (int k = 0; k < 64; k++)
            Ws[k * NOUT + f] = W[(size_t)(kk + k) * NOUT + f];
        __syncthreads();

        const float4* As4 = reinterpret_cast<const float4*>(As);
        for (int k4 = 0; k4 < 16; k4++) {
            float w0 = Ws[(k4 * 4 + 0) * NOUT + f];
            float w1 = Ws[(k4 * 4 + 1) * NOUT + f];
            float w2 = Ws[(k4 * 4 + 2) * NOUT + f];
            float w3 = Ws[(k4 * 4 + 3) * NOUT + f];
#pragma unroll
            for (int r = 0; r < 32; r++) {
                float4 a = As4[r * 16 + k4];
                acc[r] = fmaf(a.x, w0, acc[r]);
                acc[r] = fmaf(a.y, w1, acc[r]);
                acc[r] = fmaf(a.z, w2, acc[r]);
                acc[r] = fmaf(a.w, w3, acc[r]);
            }
        }
        __syncthreads();
    }

#pragma unroll
    for (int r = 0; r < 32; r++) {
        int row = row0 + r;
        if (row < n) {
            float val = g_dinv[row] * acc[r];
            s_out[(size_t)row * NOUT + f]   = val;
            agg_out[(size_t)row * NOUT + f] = val;  // self-loop contribution
        }
    }
}

// ---- edge scatter: agg[dst] += s[src] ---------------------------------------
template <int F, int LAYER>
__global__ void k_scatter(const int* __restrict__ w, int E)
{
    const float* s   = (LAYER == 1) ? g_s1 : g_s2;
    float*       agg = (LAYER == 1) ? g_agg1 : g_agg2;

    const int is64 = g_is64;
    const int* es = w;
    const int* ed = w + (size_t)E * (1 + is64);

    const int lane = threadIdx.x & 31;
    const int warp = (blockIdx.x * blockDim.x + threadIdx.x) >> 5;
    const int nwarp = (gridDim.x * blockDim.x) >> 5;

    for (long long base = (long long)warp * 32; base < E; base += (long long)nwarp * 32) {
        long long e = base + lane;
        int u = 0, v = 0;
        if (e < (long long)E) {
            u = edge_at(es, e, is64);
            v = edge_at(ed, e, is64);
        }
        int cnt = (int)min((long long)32, (long long)E - base);
        for (int i = 0; i < cnt; i++) {
            int uu = __shfl_sync(0xffffffffu, u, i);
            int vv = __shfl_sync(0xffffffffu, v, i);
            if (F == 128) {
                const float4* sp = reinterpret_cast<const float4*>(s + (size_t)uu * 128);
                float4 val = sp[lane];
                float* ap = agg + (size_t)vv * 128 + lane * 4;
                atomicAdd(ap + 0, val.x);
                atomicAdd(ap + 1, val.y);
                atomicAdd(ap + 2, val.z);
                atomicAdd(ap + 3, val.w);
            } else {
                const float2* sp = reinterpret_cast<const float2*>(s + (size_t)uu * 64);
                float2 val = sp[lane];
                float* ap = agg + (size_t)vv * 64 + lane * 2;
                atomicAdd(ap + 0, val.x);
                atomicAdd(ap + 1, val.y);
            }
        }
    }
}

// ---- final epilogue ----------------------------------------------------------
__global__ void k_final(const float* __restrict__ b, float* __restrict__ out, int n)
{
    int i = blockIdx.x * blockDim.x + threadIdx.x;
    if (i < n * ODIM) {
        int row = i >> 6, f = i & 63;
        out[i] = g_dinv[row] * g_agg2[i] + b[f];
    }
}

// -----------------------------------------------------------------------------
extern "C" void kernel_launch(void* const* d_in, const int* in_sizes, int n_in,
                              void* d_out, int out_size)
{
    const float* x  = (const float*)d_in[0];
    const int*   ew = (const int*)d_in[1];   // raw words of edge_index
    const float* W1 = (const float*)d_in[2];
    const float* b1 = (const float*)d_in[3];
    const float* W2 = (const float*)d_in[4];
    const float* b2 = (const float*)d_in[5];

    const int n = in_sizes[0] / HID;        // 100000
    const int E = in_sizes[1] / 2;          // 1600000

    k_detect<<<1, 256>>>(ew);

    // degrees (float counts are exact) -> dinv in place
    k_fill1<<<(n + 255) / 256, 256>>>(n);
    k_count<<<(E + 255) / 256, 256>>>(ew, E);
    k_rsqrt<<<(n + 255) / 256, 256>>>(n);

    // layer 1
    k_gemm<HID, 1><<<(n + 31) / 32, HID>>>(x, W1, nullptr, n);
    k_scatter<HID, 1><<<2048, 256>>>(ew, E);

    // layer 2 (layer-1 finalize fused into A-tile load)
    k_gemm<ODIM, 2><<<(n + 31) / 32, ODIM>>>(nullptr, W2, b1, n);
    k_scatter<ODIM, 2><<<2048, 256>>>(ew, E);

    k_final<<<(n * ODIM + 255) / 256, 256>>>(b2, (float*)d_out, n);
}

// round 5
// speedup vs baseline: 2.4254x; 2.4254x over previous
#include <cuda_runtime.h>
#include <cstddef>

// ---------------------------------------------------------------------------
// 2-layer GCN:  out = Norm (Norm (X W1) + b1) W2 + b2, Norm = D^-1/2 (A+I) D^-1/2
// Per layer:   s[i] = dinv[i] * (A_in @ W)[i]
//              agg[d] = s[d] + sum_{(u->d)} s[u]      (CSR gather, no fp atomics)
//              h[i] = dinv[i] * agg[i] + b
// Dst-CSR built once per launch, reused by both layers.
// Scratch = __device__ globals referenced only from device code.
// ---------------------------------------------------------------------------

#define NMAX 100000
#define EMAX 1700000
#define HID 128
#define ODIM 64
#define SCAN_BLK 512

__device__ float g_dinv[NMAX];
__device__ float g_s1[(size_t)NMAX * HID];
__device__ float g_agg1[(size_t)NMAX * HID];
__device__ float g_s2[(size_t)NMAX * ODIM];
__device__ int   g_is64;

__device__ int g_cnt[NMAX];
__device__ int g_rowptr[NMAX + 1];
__device__ int g_cursor[NMAX];
__device__ int g_csr[EMAX];
__device__ int g_bsum[1024];

// ---- dtype detection (int32 vs int64 edge_index) ---------------------------
__global__ void k_detect(const int* __restrict__ w) {
    __shared__ int any;
    if (threadIdx.x == 0) any = 0;
    __syncthreads();
    for (int i = threadIdx.x; i < 2048; i += blockDim.x)
        if (w[2 * i + 1] != 0) any = 1;
    __syncthreads();
    if (threadIdx.x == 0) g_is64 = (any == 0) ? 1 : 0;
}

__device__ __forceinline__ int edge_at(const int* __restrict__ w, int i, int is64) {
    return is64 ? w[2 * (size_t)i] : w[i];
}

// ---- CSR build --------------------------------------------------------------
__global__ void k_zero(int n) {
    int i = blockIdx.x * blockDim.x + threadIdx.x;
    if (i < n) g_cnt[i] = 0;
}

__global__ void k_count(const int* __restrict__ w, int E) {
    int is64 = g_is64;
    const int* dst = w + (size_t)E * (1 + is64);
    int i = blockIdx.x * blockDim.x + threadIdx.x;
    if (i < E) atomicAdd(&g_cnt[edge_at(dst, i, is64)], 1);
}

// block-local exclusive scan; block totals to g_bsum
__global__ void k_scan1(int n) {
    __shared__ int sh[SCAN_BLK];
    int i = blockIdx.x * SCAN_BLK + threadIdx.x;
    int v = (i < n) ? g_cnt[i] : 0;
    sh[threadIdx.x] = v;
    __syncthreads();
    for (int off = 1; off < SCAN_BLK; off <<= 1) {
        int t = (threadIdx.x >= off) ? sh[threadIdx.x - off] : 0;
        __syncthreads();
        sh[threadIdx.x] += t;
        __syncthreads();
    }
    if (i < n) g_rowptr[i] = sh[threadIdx.x] - v;  // exclusive
    if (threadIdx.x == SCAN_BLK - 1) g_bsum[blockIdx.x] = sh[SCAN_BLK - 1];
}

// scan of block sums (nblk <= 1024), single block
__global__ void k_scan2(int nblk) {
    __shared__ int sh[1024];
    int v = (threadIdx.x < nblk) ? g_bsum[threadIdx.x] : 0;
    sh[threadIdx.x] = v;
    __syncthreads();
    for (int off = 1; off < 1024; off <<= 1) {
        int t = (threadIdx.x >= off) ? sh[threadIdx.x - off] : 0;
        __syncthreads();
        sh[threadIdx.x] += t;
        __syncthreads();
    }
    if (threadIdx.x < nblk) g_bsum[threadIdx.x] = sh[threadIdx.x] - v;  // exclusive
}

// finalize row_ptr, cursor, dinv
__global__ void k_scan3(int n, int E) {
    int i = blockIdx.x * blockDim.x + threadIdx.x;
    if (i < n) {
        int rp = g_rowptr[i] + g_bsum[i / SCAN_BLK];
        g_rowptr[i] = rp;
        g_cursor[i] = rp;
        g_dinv[i]   = rsqrtf((float)g_cnt[i] + 1.0f);  // + self loop
        if (i == n - 1) g_rowptr[n] = E;
    }
}

__global__ void k_fill(const int* __restrict__ w, int E) {
    int is64 = g_is64;
    const int* src = w;
    const int* dst = w + (size_t)E * (1 + is64);
    int i = blockIdx.x * blockDim.x + threadIdx.x;
    if (i < E) {
        int u = edge_at(src, i, is64);
        int v = edge_at(dst, i, is64);
        int pos = atomicAdd(&g_cursor[v], 1);
        g_csr[pos] = u;
    }
}

// ---- GEMM (K=128 fixed), fused input transform + output dinv scale ---------
// LAYER==1: A = x, out -> g_s1.    LAYER==2: A = g_agg1 with dinv*v+b1 fused, out -> g_s2.
template <int NOUT, int LAYER>
__global__ void __launch_bounds__(NOUT) k_gemm(
    const float* __restrict__ A_in, const float* __restrict__ W,
    const float* __restrict__ bias, int n)
{
    const float* A     = (LAYER == 1) ? A_in : g_agg1;
    float*       s_out = (LAYER == 1) ? g_s1 : g_s2;

    __shared__ float As[32 * 64];
    __shared__ float Ws[64 * NOUT];
    const int f = threadIdx.x;
    const int row0 = blockIdx.x * 32;

    float acc[32];
#pragma unroll
    for (int r = 0; r < 32; r++) acc[r] = 0.0f;

    for (int kk = 0; kk < 128; kk += 64) {
        for (int idx = f; idx < 32 * 64; idx += NOUT) {
            int r = idx >> 6, c = idx & 63;
            int row = row0 + r;
            float v = 0.0f;
            if (row < n) {
                v = A[(size_t)row * 128 + kk + c];
                if (LAYER == 2) v = g_dinv[row] * v + bias[kk + c];
            }
            As[idx] = v;
        }
        for (int k = 0; k < 64; k++)
            Ws[k * NOUT + f] = W[(size_t)(kk + k) * NOUT + f];
        __syncthreads();

        const float4* As4 = reinterpret_cast<const float4*>(As);
        for (int k4 = 0; k4 < 16; k4++) {
            float w0 = Ws[(k4 * 4 + 0) * NOUT + f];
            float w1 = Ws[(k4 * 4 + 1) * NOUT + f];
            float w2 = Ws[(k4 * 4 + 2) * NOUT + f];
            float w3 = Ws[(k4 * 4 + 3) * NOUT + f];
#pragma unroll
            for (int r = 0; r < 32; r++) {
                float4 a = As4[r * 16 + k4];
                acc[r] = fmaf(a.x, w0, acc[r]);
                acc[r] = fmaf(a.y, w1, acc[r]);
                acc[r] = fmaf(a.z, w2, acc[r]);
                acc[r] = fmaf(a.w, w3, acc[r]);
            }
        }
        __syncthreads();
    }

#pragma unroll
    for (int r = 0; r < 32; r++) {
        int row = row0 + r;
        if (row < n)
            s_out[(size_t)row * NOUT + f] = g_dinv[row] * acc[r];
    }
}

// ---- CSR gather: one warp per destination row -------------------------------
// LAYER==1: agg1[d] = s1[d] + sum s1[u]           (float4 lanes, F=128)
// LAYER==2: out[d]  = dinv[d]*(s2[d]+sum) + b2[f] (float2 lanes, F=64)
template <int LAYER>
__global__ void k_gather(const float* __restrict__ b2, float* __restrict__ out, int n)
{
    const int lane = threadIdx.x & 31;
    const int wid  = (blockIdx.x * blockDim.x + threadIdx.x) >> 5;
    if (wid >= n) return;

    const int beg = g_rowptr[wid];
    const int end = g_rowptr[wid + 1];

    if (LAYER == 1) {
        const float4* sp = reinterpret_cast<const float4*>(g_s1);
        float4 a0 = sp[(size_t)wid * 32 + lane];       // self loop
        float4 a1 = make_float4(0.f, 0.f, 0.f, 0.f);
        float4 a2 = make_float4(0.f, 0.f, 0.f, 0.f);
        float4 a3 = make_float4(0.f, 0.f, 0.f, 0.f);
        int j = beg;
        for (; j + 4 <= end; j += 4) {
            int u0 = g_csr[j], u1 = g_csr[j + 1], u2 = g_csr[j + 2], u3 = g_csr[j + 3];
            float4 v0 = sp[(size_t)u0 * 32 + lane];
            float4 v1 = sp[(size_t)u1 * 32 + lane];
            float4 v2 = sp[(size_t)u2 * 32 + lane];
            float4 v3 = sp[(size_t)u3 * 32 + lane];
            a0.x += v0.x; a0.y += v0.y; a0.z += v0.z; a0.w += v0.w;
            a1.x += v1.x; a1.y += v1.y; a1.z += v1.z; a1.w += v1.w;
            a2.x += v2.x; a2.y += v2.y; a2.z += v2.z; a2.w += v2.w;
            a3.x += v3.x; a3.y += v3.y; a3.z += v3.z; a3.w += v3.w;
        }
        for (; j < end; j++) {
            float4 v = sp[(size_t)g_csr[j] * 32 + lane];
            a0.x += v.x; a0.y += v.y; a0.z += v.z; a0.w += v.w;
        }
        a0.x += a1.x + a2.x + a3.x;
        a0.y += a1.y + a2.y + a3.y;
        a0.z += a1.z + a2.z + a3.z;
        a0.w += a1.w + a2.w + a3.w;
        reinterpret_cast<float4*>(g_agg1)[(size_t)wid * 32 + lane] = a0;
    } else {
        const float2* sp = reinterpret_cast<const float2*>(g_s2);
        float2 a0 = sp[(size_t)wid * 32 + lane];       // self loop
        float2 a1 = make_float2(0.f, 0.f);
        float2 a2 = make_float2(0.f, 0.f);
        float2 a3 = make_float2(0.f, 0.f);
        int j = beg;
        for (; j + 4 <= end; j += 4) {
            int u0 = g_csr[j], u1 = g_csr[j + 1], u2 = g_csr[j + 2], u3 = g_csr[j + 3];
            float2 v0 = sp[(size_t)u0 * 32 + lane];
            float2 v1 = sp[(size_t)u1 * 32 + lane];
            float2 v2 = sp[(size_t)u2 * 32 + lane];
            float2 v3 = sp[(size_t)u3 * 32 + lane];
            a0.x += v0.x; a0.y += v0.y;
            a1.x += v1.x; a1.y += v1.y;
            a2.x += v2.x; a2.y += v2.y;
            a3.x += v3.x; a3.y += v3.y;
        }
        for (; j < end; j++) {
            float2 v = sp[(size_t)g_csr[j] * 32 + lane];
            a0.x += v.x; a0.y += v.y;
        }
        a0.x += a1.x + a2.x + a3.x;
        a0.y += a1.y + a2.y + a3.y;
        float di = g_dinv[wid];
        float2 r;
        r.x = di * a0.x + b2[lane * 2 + 0];
        r.y = di * a0.y + b2[lane * 2 + 1];
        reinterpret_cast<float2*>(out)[(size_t)wid * 32 + lane] = r;
    }
}

// -----------------------------------------------------------------------------
extern "C" void kernel_launch(void* const* d_in, const int* in_sizes, int n_in,
                              void* d_out, int out_size)
{
    const float* x  = (const float*)d_in[0];
    const int*   ew = (const int*)d_in[1];
    const float* W1 = (const float*)d_in[2];
    const float* b1 = (const float*)d_in[3];
    const float* W2 = (const float*)d_in[4];
    const float* b2 = (const float*)d_in[5];

    const int n = in_sizes[0] / HID;   // 100000
    const int E = in_sizes[1] / 2;     // 1600000
    const int nblk_scan = (n + SCAN_BLK - 1) / SCAN_BLK;

    k_detect<<<1, 256>>>(ew);

    // CSR build + dinv
    k_zero<<<(n + 255) / 256, 256>>>(n);
    k_count<<<(E + 255) / 256, 256>>>(ew, E);
    k_scan1<<<nblk_scan, SCAN_BLK>>>(n);
    k_scan2<<<1, 1024>>>(nblk_scan);
    k_scan3<<<(n + 255) / 256, 256>>>(n, E);
    k_fill<<<(E + 255) / 256, 256>>>(ew, E);

    // layer 1
    k_gemm<HID, 1><<<(n + 31) / 32, HID>>>(x, W1, nullptr, n);
    k_gather<1><<<(n + 7) / 8, 256>>>(nullptr, nullptr, n);

    // layer 2 (layer-1 finalize fused into GEMM A-load; epilogue fused into gather)
    k_gemm<ODIM, 2><<<(n + 31) / 32, ODIM>>>(nullptr, W2, b1, n);
    k_gather<2><<<(n + 7) / 8, 256>>>(b2, (float*)d_out, n);
}

// round 6
// speedup vs baseline: 2.8464x; 1.1736x over previous
#include <cuda_runtime.h>
#include <cuda_bf16.h>
#include <cstddef>
#include <cstdint>

// ---------------------------------------------------------------------------
// 2-layer GCN. Per layer:  s = dinv * (A @ W);  agg[d] = s[d] + sum s[u];
//                          h = dinv * agg + b
// GEMMs on tensor cores (mma.sync bf16, hi/lo split = 3 MMAs, ~fp32 precision).
// Edge phase = dst-CSR gather (no fp atomics), CSR built once per launch.
// ---------------------------------------------------------------------------

#define NMAX 100000
#define EMAX 1700000
#define HID 128
#define ODIM 64
#define SCAN_BLK 512
#define KP 136   // padded K stride in bf16 elems (conflict-free frag LDS)

__device__ float g_dinv[NMAX];
__device__ float g_s1[(size_t)NMAX * HID];
__device__ float g_agg1[(size_t)NMAX * HID];
__device__ float g_s2[(size_t)NMAX * ODIM];
__device__ int   g_is64;

__device__ int g_cnt[NMAX];
__device__ int g_rowptr[NMAX + 1];
__device__ int g_cursor[NMAX];
__device__ int g_csr[EMAX];
__device__ int g_bsum[1024];

__device__ __nv_bfloat16 g_w1t_hi[HID * HID], g_w1t_lo[HID * HID];   // [n][k]
__device__ __nv_bfloat16 g_w2t_hi[ODIM * HID], g_w2t_lo[ODIM * HID]; // [n][k]

// ---- dtype detection (int32 vs int64 edge_index) ---------------------------
__global__ void k_detect(const int* __restrict__ w) {
    __shared__ int any;
    if (threadIdx.x == 0) any = 0;
    __syncthreads();
    for (int i = threadIdx.x; i < 2048; i += blockDim.x)
        if (w[2 * i + 1] != 0) any = 1;
    __syncthreads();
    if (threadIdx.x == 0) g_is64 = (any == 0) ? 1 : 0;
}

__device__ __forceinline__ int edge_at(const int* __restrict__ w, int i, int is64) {
    return is64 ? w[2 * (size_t)i] : w[i];
}

// ---- CSR build --------------------------------------------------------------
__global__ void k_zero(int n) {
    int i = blockIdx.x * blockDim.x + threadIdx.x;
    if (i < n) g_cnt[i] = 0;
}

__global__ void k_count(const int* __restrict__ w, int E) {
    int is64 = g_is64;
    const int* dst = w + (size_t)E * (1 + is64);
    int i = blockIdx.x * blockDim.x + threadIdx.x;
    if (i < E) atomicAdd(&g_cnt[edge_at(dst, i, is64)], 1);
}

__global__ void k_scan1(int n) {
    __shared__ int sh[SCAN_BLK];
    int i = blockIdx.x * SCAN_BLK + threadIdx.x;
    int v = (i < n) ? g_cnt[i] : 0;
    sh[threadIdx.x] = v;
    __syncthreads();
    for (int off = 1; off < SCAN_BLK; off <<= 1) {
        int t = (threadIdx.x >= off) ? sh[threadIdx.x - off] : 0;
        __syncthreads();
        sh[threadIdx.x] += t;
        __syncthreads();
    }
    if (i < n) g_rowptr[i] = sh[threadIdx.x] - v;
    if (threadIdx.x == SCAN_BLK - 1) g_bsum[blockIdx.x] = sh[SCAN_BLK - 1];
}

__global__ void k_scan2(int nblk) {
    __shared__ int sh[1024];
    int v = (threadIdx.x < nblk) ? g_bsum[threadIdx.x] : 0;
    sh[threadIdx.x] = v;
    __syncthreads();
    for (int off = 1; off < 1024; off <<= 1) {
        int t = (threadIdx.x >= off) ? sh[threadIdx.x - off] : 0;
        __syncthreads();
        sh[threadIdx.x] += t;
        __syncthreads();
    }
    if (threadIdx.x < nblk) g_bsum[threadIdx.x] = sh[threadIdx.x] - v;
}

__global__ void k_scan3(int n, int E) {
    int i = blockIdx.x * blockDim.x + threadIdx.x;
    if (i < n) {
        int rp = g_rowptr[i] + g_bsum[i / SCAN_BLK];
        g_rowptr[i] = rp;
        g_cursor[i] = rp;
        g_dinv[i]   = rsqrtf((float)g_cnt[i] + 1.0f);
        if (i == n - 1) g_rowptr[n] = E;
    }
}

__global__ void k_fill(const int* __restrict__ w, int E) {
    int is64 = g_is64;
    const int* src = w;
    const int* dst = w + (size_t)E * (1 + is64);
    int i = blockIdx.x * blockDim.x + threadIdx.x;
    if (i < E) {
        int u = edge_at(src, i, is64);
        int v = edge_at(dst, i, is64);
        int pos = atomicAdd(&g_cursor[v], 1);
        g_csr[pos] = u;
    }
}

// ---- W -> transposed bf16 hi/lo ----------------------------------------------
__global__ void k_convw(const float* __restrict__ W1, const float* __restrict__ W2) {
    int i = blockIdx.x * blockDim.x + threadIdx.x;
    if (i < HID * HID) {
        int nn = i >> 7, k = i & 127;
        float v = W1[k * HID + nn];
        __nv_bfloat16 h = __float2bfloat16(v);
        g_w1t_hi[i] = h;
        g_w1t_lo[i] = __float2bfloat16(v - __bfloat162float(h));
    }
    if (i < ODIM * HID) {
        int nn = i >> 7, k = i & 127;
        float v = W2[k * ODIM + nn];
        __nv_bfloat16 h = __float2bfloat16(v);
        g_w2t_hi[i] = h;
        g_w2t_lo[i] = __float2bfloat16(v - __bfloat162float(h));
    }
}

// ---- tensor-core GEMM ---------------------------------------------------------
__device__ __forceinline__ void mma16816(float c[4], const uint32_t a[4], const uint32_t b[2]) {
    asm volatile(
        "mma.sync.aligned.m16n8k16.row.col.f32.bf16.bf16.f32 "
        "{%0,%1,%2,%3}, {%4,%5,%6,%7}, {%8,%9}, {%0,%1,%2,%3};\n"
        : "+f"(c[0]), "+f"(c[1]), "+f"(c[2]), "+f"(c[3])
        : "r"(a[0]), "r"(a[1]), "r"(a[2]), "r"(a[3]), "r"(b[0]), "r"(b[1]));
}

__device__ __forceinline__ uint32_t pack_bf2(__nv_bfloat16 a, __nv_bfloat16 b) {
    return (uint32_t)__bfloat16_as_ushort(a) | ((uint32_t)__bfloat16_as_ushort(b) << 16);
}

// Block: 128 rows x NOUT cols, 256 threads (8 warps, each warp m16 x NOUT).
// LAYER==1: A = x.  LAYER==2: A = g_agg1 with dinv*v + b1 fused on load.
// Epilogue: s_out = dinv[row] * acc.
template <int NOUT, int LAYER>
__global__ void __launch_bounds__(256) k_tgemm(
    const float* __restrict__ A_in, const float* __restrict__ bias, int n)
{
    constexpr int NT = NOUT / 8;
    extern __shared__ __nv_bfloat16 sm[];
    __nv_bfloat16* Ahi = sm;                    // [128][KP]
    __nv_bfloat16* Alo = Ahi + 128 * KP;
    __nv_bfloat16* Bhi = Alo + 128 * KP;        // [NOUT][KP]
    __nv_bfloat16* Blo = Bhi + NOUT * KP;

    const float* A     = (LAYER == 1) ? A_in : g_agg1;
    float*       s_out = (LAYER == 1) ? g_s1 : g_s2;
    const __nv_bfloat16* Wh = (LAYER == 1) ? g_w1t_hi : g_w2t_hi;
    const __nv_bfloat16* Wl = (LAYER == 1) ? g_w1t_lo : g_w2t_lo;

    const int tid  = threadIdx.x;
    const int row0 = blockIdx.x * 128;

    // stage A tile (fp32 -> bf16 hi/lo), fused layer-2 input transform
    for (int base = tid * 4; base < 128 * 128; base += 256 * 4) {
        int r = base >> 7, k = base & 127;
        int row = row0 + r;
        float4 v = make_float4(0.f, 0.f, 0.f, 0.f);
        if (row < n) {
            v = *reinterpret_cast<const float4*>(&A[(size_t)row * 128 + k]);
            if (LAYER == 2) {
                float d = g_dinv[row];
                float4 bb = *reinterpret_cast<const float4*>(&bias[k]);
                v.x = fmaf(d, v.x, bb.x); v.y = fmaf(d, v.y, bb.y);
                v.z = fmaf(d, v.z, bb.z); v.w = fmaf(d, v.w, bb.w);
            }
        }
        __nv_bfloat16 h0 = __float2bfloat16(v.x), h1 = __float2bfloat16(v.y);
        __nv_bfloat16 h2 = __float2bfloat16(v.z), h3 = __float2bfloat16(v.w);
        __nv_bfloat16 l0 = __float2bfloat16(v.x - __bfloat162float(h0));
        __nv_bfloat16 l1 = __float2bfloat16(v.y - __bfloat162float(h1));
        __nv_bfloat16 l2 = __float2bfloat16(v.z - __bfloat162float(h2));
        __nv_bfloat16 l3 = __float2bfloat16(v.w - __bfloat162float(h3));
        *reinterpret_cast<uint2*>(&Ahi[r * KP + k]) = make_uint2(pack_bf2(h0, h1), pack_bf2(h2, h3));
        *reinterpret_cast<uint2*>(&Alo[r * KP + k]) = make_uint2(pack_bf2(l0, l1), pack_bf2(l2, l3));
    }
    // stage B tile (already bf16 hi/lo, transposed [n][k])
    for (int base = tid * 8; base < NOUT * 128; base += 256 * 8) {
        int nn = base >> 7, k = base & 127;
        *reinterpret_cast<uint4*>(&Bhi[nn * KP + k]) = *reinterpret_cast<const uint4*>(&Wh[base]);
        *reinterpret_cast<uint4*>(&Blo[nn * KP + k]) = *reinterpret_cast<const uint4*>(&Wl[base]);
    }
    __syncthreads();

    const int w = tid >> 5, lane = tid & 31;
    const int g = lane >> 2, tq = lane & 3;
    const int mrow = w * 16;

    float acc[NT][4];
#pragma unroll
    for (int nt = 0; nt < NT; nt++)
#pragma unroll
        for (int j = 0; j < 4; j++) acc[nt][j] = 0.0f;

#pragma unroll
    for (int kt = 0; kt < 8; kt++) {
        const int k0 = kt * 16;
        uint32_t ah[4], al[4];
        const int ra = (mrow + g) * KP + k0 + tq * 2;
        const int rb = (mrow + g + 8) * KP + k0 + tq * 2;
        ah[0] = *reinterpret_cast<const uint32_t*>(&Ahi[ra]);
        ah[1] = *reinterpret_cast<const uint32_t*>(&Ahi[rb]);
        ah[2] = *reinterpret_cast<const uint32_t*>(&Ahi[ra + 8]);
        ah[3] = *reinterpret_cast<const uint32_t*>(&Ahi[rb + 8]);
        al[0] = *reinterpret_cast<const uint32_t*>(&Alo[ra]);
        al[1] = *reinterpret_cast<const uint32_t*>(&Alo[rb]);
        al[2] = *reinterpret_cast<const uint32_t*>(&Alo[ra + 8]);
        al[3] = *reinterpret_cast<const uint32_t*>(&Alo[rb + 8]);
#pragma unroll
        for (int nt = 0; nt < NT; nt++) {
            uint32_t bh[2], bl[2];
            const int rn = (nt * 8 + g) * KP + k0 + tq * 2;
            bh[0] = *reinterpret_cast<const uint32_t*>(&Bhi[rn]);
            bh[1] = *reinterpret_cast<const uint32_t*>(&Bhi[rn + 8]);
            bl[0] = *reinterpret_cast<const uint32_t*>(&Blo[rn]);
            bl[1] = *reinterpret_cast<const uint32_t*>(&Blo[rn + 8]);
            mma16816(acc[nt], ah, bh);
            mma16816(acc[nt], ah, bl);
            mma16816(acc[nt], al, bh);
        }
    }

    const int r0g = row0 + mrow + g;
    const int r1g = r0g + 8;
    const float d0 = (r0g < n) ? g_dinv[r0g] : 0.f;
    const float d1 = (r1g < n) ? g_dinv[r1g] : 0.f;
#pragma unroll
    for (int nt = 0; nt < NT; nt++) {
        if (r0g < n) {
            float2 o = make_float2(d0 * acc[nt][0], d0 * acc[nt][1]);
            *reinterpret_cast<float2*>(&s_out[(size_t)r0g * NOUT + nt * 8 + tq * 2]) = o;
        }
        if (r1g < n) {
            float2 o = make_float2(d1 * acc[nt][2], d1 * acc[nt][3]);
            *reinterpret_cast<float2*>(&s_out[(size_t)r1g * NOUT + nt * 8 + tq * 2]) = o;
        }
    }
}

// ---- CSR gather: one warp per destination row ---------------------------------
template <int LAYER>
__global__ void k_gather(const float* __restrict__ b2, float* __restrict__ out, int n)
{
    const int lane = threadIdx.x & 31;
    const int wid  = (blockIdx.x * blockDim.x + threadIdx.x) >> 5;
    if (wid >= n) return;

    const int beg = g_rowptr[wid];
    const int end = g_rowptr[wid + 1];

    if (LAYER == 1) {
        const float4* sp = reinterpret_cast<const float4*>(g_s1);
        float4 a0 = sp[(size_t)wid * 32 + lane];  // self loop
        float4 a1 = make_float4(0.f, 0.f, 0.f, 0.f);
        float4 a2 = make_float4(0.f, 0.f, 0.f, 0.f);
        float4 a3 = make_float4(0.f, 0.f, 0.f, 0.f);
        int j = beg;
        for (; j + 4 <= end; j += 4) {
            int u0 = g_csr[j], u1 = g_csr[j + 1], u2 = g_csr[j + 2], u3 = g_csr[j + 3];
            float4 v0 = sp[(size_t)u0 * 32 + lane];
            float4 v1 = sp[(size_t)u1 * 32 + lane];
            float4 v2 = sp[(size_t)u2 * 32 + lane];
            float4 v3 = sp[(size_t)u3 * 32 + lane];
            a0.x += v0.x; a0.y += v0.y; a0.z += v0.z; a0.w += v0.w;
            a1.x += v1.x; a1.y += v1.y; a1.z += v1.z; a1.w += v1.w;
            a2.x += v2.x; a2.y += v2.y; a2.z += v2.z; a2.w += v2.w;
            a3.x += v3.x; a3.y += v3.y; a3.z += v3.z; a3.w += v3.w;
        }
        for (; j < end; j++) {
            float4 v = sp[(size_t)g_csr[j] * 32 + lane];
            a0.x += v.x; a0.y += v.y; a0.z += v.z; a0.w += v.w;
        }
        a0.x += a1.x + a2.x + a3.x;
        a0.y += a1.y + a2.y + a3.y;
        a0.z += a1.z + a2.z + a3.z;
        a0.w += a1.w + a2.w + a3.w;
        reinterpret_cast<float4*>(g_agg1)[(size_t)wid * 32 + lane] = a0;
    } else {
        const float2* sp = reinterpret_cast<const float2*>(g_s2);
        float2 a0 = sp[(size_t)wid * 32 + lane];  // self loop
        float2 a1 = make_float2(0.f, 0.f);
        float2 a2 = make_float2(0.f, 0.f);
        float2 a3 = make_float2(0.f, 0.f);
        int j = beg;
        for (; j + 4 <= end; j += 4) {
            int u0 = g_csr[j], u1 = g_csr[j + 1], u2 = g_csr[j + 2], u3 = g_csr[j + 3];
            float2 v0 = sp[(size_t)u0 * 32 + lane];
            float2 v1 = sp[(size_t)u1 * 32 + lane];
            float2 v2 = sp[(size_t)u2 * 32 + lane];
            float2 v3 = sp[(size_t)u3 * 32 + lane];
            a0.x += v0.x; a0.y += v0.y;
            a1.x += v1.x; a1.y += v1.y;
            a2.x += v2.x; a2.y += v2.y;
            a3.x += v3.x; a3.y += v3.y;
        }
        for (; j < end; j++) {
            float2 v = sp[(size_t)g_csr[j] * 32 + lane];
            a0.x += v.x; a0.y += v.y;
        }
        a0.x += a1.x + a2.x + a3.x;
        a0.y += a1.y + a2.y + a3.y;
        float di = g_dinv[wid];
        float2 r;
        r.x = di * a0.x + b2[lane * 2 + 0];
        r.y = di * a0.y + b2[lane * 2 + 1];
        reinterpret_cast<float2*>(out)[(size_t)wid * 32 + lane] = r;
    }
}

// -----------------------------------------------------------------------------
extern "C" void kernel_launch(void* const* d_in, const int* in_sizes, int n_in,
                              void* d_out, int out_size)
{
    const float* x  = (const float*)d_in[0];
    const int*   ew = (const int*)d_in[1];
    const float* W1 = (const float*)d_in[2];
    const float* b1 = (const float*)d_in[3];
    const float* W2 = (const float*)d_in[4];
    const float* b2 = (const float*)d_in[5];

    const int n = in_sizes[0] / HID;   // 100000
    const int E = in_sizes[1] / 2;     // 1600000
    const int nblk_scan = (n + SCAN_BLK - 1) / SCAN_BLK;

    const int smem1 = (2 * 128 * KP + 2 * HID * KP) * 2;   // 139264 B
    const int smem2 = (2 * 128 * KP + 2 * ODIM * KP) * 2;  // 104448 B
    cudaFuncSetAttribute(k_tgemm<HID, 1>, cudaFuncAttributeMaxDynamicSharedMemorySize, smem1);
    cudaFuncSetAttribute(k_tgemm<ODIM, 2>, cudaFuncAttributeMaxDynamicSharedMemorySize, smem2);

    k_detect<<<1, 256>>>(ew);

    // CSR build + dinv
    k_zero<<<(n + 255) / 256, 256>>>(n);
    k_count<<<(E + 255) / 256, 256>>>(ew, E);
    k_scan1<<<nblk_scan, SCAN_BLK>>>(n);
    k_scan2<<<1, 1024>>>(nblk_scan);
    k_scan3<<<(n + 255) / 256, 256>>>(n, E);
    k_fill<<<(E + 255) / 256, 256>>>(ew, E);

    k_convw<<<(HID * HID + 255) / 256, 256>>>(W1, W2);

    const int gblk = (n + 127) / 128;
    // layer 1
    k_tgemm<HID, 1><<<gblk, 256, smem1>>>(x, nullptr, n);
    k_gather<1><<<(n + 7) / 8, 256>>>(nullptr, nullptr, n);

    // layer 2 (bias = b1 fused into A staging; epilogue fused into gather)
    k_tgemm<ODIM, 2><<<gblk, 256, smem2>>>(nullptr, b1, n);
    k_gather<2><<<(n + 7) / 8, 256>>>(b2, (float*)d_out, n);
}

// round 7
// speedup vs baseline: 2.9741x; 1.0448x over previous
#include <cuda_runtime.h>
#include <cuda_bf16.h>
#include <cuda_fp16.h>
#include <cstddef>
#include <cstdint>

// ---------------------------------------------------------------------------
// 2-layer GCN. Per layer:  s = dinv * (A @ W);  agg[d] = s[d] + sum s[u];
//                          h = dinv * agg + b
// GEMMs: mma.sync bf16 hi/lo split (3 MMAs, ~fp32 precision).
// Edge phase: dst-CSR gather, message payload stored fp16 (halves L2 traffic),
// accumulation in fp32.
// ---------------------------------------------------------------------------

#define NMAX 100000
#define EMAX 1700000
#define HID 128
#define ODIM 64
#define SCAN_BLK 512
#define KP 136   // padded K stride in bf16 elems (conflict-free frag LDS)

__device__ float  g_dinv[NMAX];
__device__ __half g_s1[(size_t)NMAX * HID];    // fp16 messages, layer 1
__device__ float  g_agg1[(size_t)NMAX * HID];  // fp32 aggregate
__device__ __half g_s2[(size_t)NMAX * ODIM];   // fp16 messages, layer 2
__device__ int    g_is64;

__device__ int g_cnt[NMAX];
__device__ int g_rowptr[NMAX + 1];
__device__ int g_cursor[NMAX];
__device__ int g_csr[EMAX];
__device__ int g_bsum[1024];

__device__ __nv_bfloat16 g_w1t_hi[HID * HID], g_w1t_lo[HID * HID];   // [n][k]
__device__ __nv_bfloat16 g_w2t_hi[ODIM * HID], g_w2t_lo[ODIM * HID]; // [n][k]

// ---- dtype detection (int32 vs int64 edge_index) ---------------------------
__global__ void k_detect(const int* __restrict__ w) {
    __shared__ int any;
    if (threadIdx.x == 0) any = 0;
    __syncthreads();
    for (int i = threadIdx.x; i < 2048; i += blockDim.x)
        if (w[2 * i + 1] != 0) any = 1;
    __syncthreads();
    if (threadIdx.x == 0) g_is64 = (any == 0) ? 1 : 0;
}

__device__ __forceinline__ int edge_at(const int* __restrict__ w, int i, int is64) {
    return is64 ? w[2 * (size_t)i] : w[i];
}

// ---- CSR build --------------------------------------------------------------
__global__ void k_zero(int n) {
    int i = blockIdx.x * blockDim.x + threadIdx.x;
    if (i < n) g_cnt[i] = 0;
}

__global__ void k_count(const int* __restrict__ w, int E) {
    int is64 = g_is64;
    const int* dst = w + (size_t)E * (1 + is64);
    int i = blockIdx.x * blockDim.x + threadIdx.x;
    if (i < E) atomicAdd(&g_cnt[edge_at(dst, i, is64)], 1);
}

__global__ void k_scan1(int n) {
    __shared__ int sh[SCAN_BLK];
    int i = blockIdx.x * SCAN_BLK + threadIdx.x;
    int v = (i < n) ? g_cnt[i] : 0;
    sh[threadIdx.x] = v;
    __syncthreads();
    for (int off = 1; off < SCAN_BLK; off <<= 1) {
        int t = (threadIdx.x >= off) ? sh[threadIdx.x - off] : 0;
        __syncthreads();
        sh[threadIdx.x] += t;
        __syncthreads();
    }
    if (i < n) g_rowptr[i] = sh[threadIdx.x] - v;
    if (threadIdx.x == SCAN_BLK - 1) g_bsum[blockIdx.x] = sh[SCAN_BLK - 1];
}

__global__ void k_scan2(int nblk) {
    __shared__ int sh[1024];
    int v = (threadIdx.x < nblk) ? g_bsum[threadIdx.x] : 0;
    sh[threadIdx.x] = v;
    __syncthreads();
    for (int off = 1; off < 1024; off <<= 1) {
        int t = (threadIdx.x >= off) ? sh[threadIdx.x - off] : 0;
        __syncthreads();
        sh[threadIdx.x] += t;
        __syncthreads();
    }
    if (threadIdx.x < nblk) g_bsum[threadIdx.x] = sh[threadIdx.x] - v;
}

__global__ void k_scan3(int n, int E) {
    int i = blockIdx.x * blockDim.x + threadIdx.x;
    if (i < n) {
        int rp = g_rowptr[i] + g_bsum[i / SCAN_BLK];
        g_rowptr[i] = rp;
        g_cursor[i] = rp;
        g_dinv[i]   = rsqrtf((float)g_cnt[i] + 1.0f);
        if (i == n - 1) g_rowptr[n] = E;
    }
}

__global__ void k_fill(const int* __restrict__ w, int E) {
    int is64 = g_is64;
    const int* src = w;
    const int* dst = w + (size_t)E * (1 + is64);
    int i = blockIdx.x * blockDim.x + threadIdx.x;
    if (i < E) {
        int u = edge_at(src, i, is64);
        int v = edge_at(dst, i, is64);
        int pos = atomicAdd(&g_cursor[v], 1);
        g_csr[pos] = u;
    }
}

// ---- W -> transposed bf16 hi/lo ----------------------------------------------
__global__ void k_convw(const float* __restrict__ W1, const float* __restrict__ W2) {
    int i = blockIdx.x * blockDim.x + threadIdx.x;
    if (i < HID * HID) {
        int nn = i >> 7, k = i & 127;
        float v = W1[k * HID + nn];
        __nv_bfloat16 h = __float2bfloat16(v);
        g_w1t_hi[i] = h;
        g_w1t_lo[i] = __float2bfloat16(v - __bfloat162float(h));
    }
    if (i < ODIM * HID) {
        int nn = i >> 7, k = i & 127;
        float v = W2[k * ODIM + nn];
        __nv_bfloat16 h = __float2bfloat16(v);
        g_w2t_hi[i] = h;
        g_w2t_lo[i] = __float2bfloat16(v - __bfloat162float(h));
    }
}

// ---- tensor-core GEMM ---------------------------------------------------------
__device__ __forceinline__ void mma16816(float c[4], const uint32_t a[4], const uint32_t b[2]) {
    asm volatile(
        "mma.sync.aligned.m16n8k16.row.col.f32.bf16.bf16.f32 "
        "{%0,%1,%2,%3}, {%4,%5,%6,%7}, {%8,%9}, {%0,%1,%2,%3};\n"
        : "+f"(c[0]), "+f"(c[1]), "+f"(c[2]), "+f"(c[3])
        : "r"(a[0]), "r"(a[1]), "r"(a[2]), "r"(a[3]), "r"(b[0]), "r"(b[1]));
}

__device__ __forceinline__ uint32_t pack_bf2(__nv_bfloat16 a, __nv_bfloat16 b) {
    return (uint32_t)__bfloat16_as_ushort(a) | ((uint32_t)__bfloat16_as_ushort(b) << 16);
}

// Block: 128 rows x NOUT cols, 256 threads (8 warps, each warp m16 x NOUT).
// LAYER==1: A = x.  LAYER==2: A = g_agg1 with dinv*v + b1 fused on load.
// Epilogue: s_out(fp16) = dinv[row] * acc.
template <int NOUT, int LAYER>
__global__ void __launch_bounds__(256) k_tgemm(
    const float* __restrict__ A_in, const float* __restrict__ bias, int n)
{
    constexpr int NT = NOUT / 8;
    extern __shared__ __nv_bfloat16 sm[];
    __nv_bfloat16* Ahi = sm;                    // [128][KP]
    __nv_bfloat16* Alo = Ahi + 128 * KP;
    __nv_bfloat16* Bhi = Alo + 128 * KP;        // [NOUT][KP]
    __nv_bfloat16* Blo = Bhi + NOUT * KP;

    const float* A     = (LAYER == 1) ? A_in : g_agg1;
    __half*      s_out = (LAYER == 1) ? g_s1 : g_s2;
    const __nv_bfloat16* Wh = (LAYER == 1) ? g_w1t_hi : g_w2t_hi;
    const __nv_bfloat16* Wl = (LAYER == 1) ? g_w1t_lo : g_w2t_lo;

    const int tid  = threadIdx.x;
    const int row0 = blockIdx.x * 128;

    // stage A tile (fp32 -> bf16 hi/lo), fused layer-2 input transform
    for (int base = tid * 4; base < 128 * 128; base += 256 * 4) {
        int r = base >> 7, k = base & 127;
        int row = row0 + r;
        float4 v = make_float4(0.f, 0.f, 0.f, 0.f);
        if (row < n) {
            v = *reinterpret_cast<const float4*>(&A[(size_t)row * 128 + k]);
            if (LAYER == 2) {
                float d = g_dinv[row];
                float4 bb = *reinterpret_cast<const float4*>(&bias[k]);
                v.x = fmaf(d, v.x, bb.x); v.y = fmaf(d, v.y, bb.y);
                v.z = fmaf(d, v.z, bb.z); v.w = fmaf(d, v.w, bb.w);
            }
        }
        __nv_bfloat16 h0 = __float2bfloat16(v.x), h1 = __float2bfloat16(v.y);
        __nv_bfloat16 h2 = __float2bfloat16(v.z), h3 = __float2bfloat16(v.w);
        __nv_bfloat16 l0 = __float2bfloat16(v.x - __bfloat162float(h0));
        __nv_bfloat16 l1 = __float2bfloat16(v.y - __bfloat162float(h1));
        __nv_bfloat16 l2 = __float2bfloat16(v.z - __bfloat162float(h2));
        __nv_bfloat16 l3 = __float2bfloat16(v.w - __bfloat162float(h3));
        *reinterpret_cast<uint2*>(&Ahi[r * KP + k]) = make_uint2(pack_bf2(h0, h1), pack_bf2(h2, h3));
        *reinterpret_cast<uint2*>(&Alo[r * KP + k]) = make_uint2(pack_bf2(l0, l1), pack_bf2(l2, l3));
    }
    // stage B tile (already bf16 hi/lo, transposed [n][k])
    for (int base = tid * 8; base < NOUT * 128; base += 256 * 8) {
        int nn = base >> 7, k = base & 127;
        *reinterpret_cast<uint4*>(&Bhi[nn * KP + k]) = *reinterpret_cast<const uint4*>(&Wh[base]);
        *reinterpret_cast<uint4*>(&Blo[nn * KP + k]) = *reinterpret_cast<const uint4*>(&Wl[base]);
    }
    __syncthreads();

    const int w = tid >> 5, lane = tid & 31;
    const int g = lane >> 2, tq = lane & 3;
    const int mrow = w * 16;

    float acc[NT][4];
#pragma unroll
    for (int nt = 0; nt < NT; nt++)
#pragma unroll
        for (int j = 0; j < 4; j++) acc[nt][j] = 0.0f;

#pragma unroll
    for (int kt = 0; kt < 8; kt++) {
        const int k0 = kt * 16;
        uint32_t ah[4], al[4];
        const int ra = (mrow + g) * KP + k0 + tq * 2;
        const int rb = (mrow + g + 8) * KP + k0 + tq * 2;
        ah[0] = *reinterpret_cast<const uint32_t*>(&Ahi[ra]);
        ah[1] = *reinterpret_cast<const uint32_t*>(&Ahi[rb]);
        ah[2] = *reinterpret_cast<const uint32_t*>(&Ahi[ra + 8]);
        ah[3] = *reinterpret_cast<const uint32_t*>(&Ahi[rb + 8]);
        al[0] = *reinterpret_cast<const uint32_t*>(&Alo[ra]);
        al[1] = *reinterpret_cast<const uint32_t*>(&Alo[rb]);
        al[2] = *reinterpret_cast<const uint32_t*>(&Alo[ra + 8]);
        al[3] = *reinterpret_cast<const uint32_t*>(&Alo[rb + 8]);
#pragma unroll
        for (int nt = 0; nt < NT; nt++) {
            uint32_t bh[2], bl[2];
            const int rn = (nt * 8 + g) * KP + k0 + tq * 2;
            bh[0] = *reinterpret_cast<const uint32_t*>(&Bhi[rn]);
            bh[1] = *reinterpret_cast<const uint32_t*>(&Bhi[rn + 8]);
            bl[0] = *reinterpret_cast<const uint32_t*>(&Blo[rn]);
            bl[1] = *reinterpret_cast<const uint32_t*>(&Blo[rn + 8]);
            mma16816(acc[nt], ah, bh);
            mma16816(acc[nt], ah, bl);
            mma16816(acc[nt], al, bh);
        }
    }

    const int r0g = row0 + mrow + g;
    const int r1g = r0g + 8;
    const float d0 = (r0g < n) ? g_dinv[r0g] : 0.f;
    const float d1 = (r1g < n) ? g_dinv[r1g] : 0.f;
#pragma unroll
    for (int nt = 0; nt < NT; nt++) {
        if (r0g < n) {
            __half2 o = __floats2half2_rn(d0 * acc[nt][0], d0 * acc[nt][1]);
            *reinterpret_cast<__half2*>(&s_out[(size_t)r0g * NOUT + nt * 8 + tq * 2]) = o;
        }
        if (r1g < n) {
            __half2 o = __floats2half2_rn(d1 * acc[nt][2], d1 * acc[nt][3]);
            *reinterpret_cast<__half2*>(&s_out[(size_t)r1g * NOUT + nt * 8 + tq * 2]) = o;
        }
    }
}

// ---- CSR gather: one warp per destination row ---------------------------------
// fp16 messages, fp32 accumulation.
// LAYER==1: lane owns 4 feats (uint2 = 2 half2), agg1(fp32) out.
// LAYER==2: lane owns 2 feats (1 half2), fused epilogue -> d_out fp32.
template <int LAYER>
__global__ void k_gather(const float* __restrict__ b2, float* __restrict__ out, int n)
{
    const int lane = threadIdx.x & 31;
    const int wid  = (blockIdx.x * blockDim.x + threadIdx.x) >> 5;
    if (wid >= n) return;

    const int beg = g_rowptr[wid];
    const int end = g_rowptr[wid + 1];

    if (LAYER == 1) {
        const uint2* sp = reinterpret_cast<const uint2*>(g_s1);  // 4 halfs per elem
        uint2 sv = sp[(size_t)wid * 32 + lane];                  // self loop
        float2 p0 = __half22float2(*reinterpret_cast<__half2*>(&sv.x));
        float2 p1 = __half22float2(*reinterpret_cast<__half2*>(&sv.y));
        float4 a0 = make_float4(p0.x, p0.y, p1.x, p1.y);
        float4 a1 = make_float4(0.f, 0.f, 0.f, 0.f);
        float4 a2 = make_float4(0.f, 0.f, 0.f, 0.f);
        float4 a3 = make_float4(0.f, 0.f, 0.f, 0.f);
        int j = beg;
        for (; j + 4 <= end; j += 4) {
            int u0 = g_csr[j], u1 = g_csr[j + 1], u2 = g_csr[j + 2], u3 = g_csr[j + 3];
            uint2 v0 = sp[(size_t)u0 * 32 + lane];
            uint2 v1 = sp[(size_t)u1 * 32 + lane];
            uint2 v2 = sp[(size_t)u2 * 32 + lane];
            uint2 v3 = sp[(size_t)u3 * 32 + lane];
            float2 q0, q1;
            q0 = __half22float2(*reinterpret_cast<__half2*>(&v0.x));
            q1 = __half22float2(*reinterpret_cast<__half2*>(&v0.y));
            a0.x += q0.x; a0.y += q0.y; a0.z += q1.x; a0.w += q1.y;
            q0 = __half22float2(*reinterpret_cast<__half2*>(&v1.x));
            q1 = __half22float2(*reinterpret_cast<__half2*>(&v1.y));
            a1.x += q0.x; a1.y += q0.y; a1.z += q1.x; a1.w += q1.y;
            q0 = __half22float2(*reinterpret_cast<__half2*>(&v2.x));
            q1 = __half22float2(*reinterpret_cast<__half2*>(&v2.y));
            a2.x += q0.x; a2.y += q0.y; a2.z += q1.x; a2.w += q1.y;
            q0 = __half22float2(*reinterpret_cast<__half2*>(&v3.x));
            q1 = __half22float2(*reinterpret_cast<__half2*>(&v3.y));
            a3.x += q0.x; a3.y += q0.y; a3.z += q1.x; a3.w += q1.y;
        }
        for (; j < end; j++) {
            uint2 v = sp[(size_t)g_csr[j] * 32 + lane];
            float2 q0 = __half22float2(*reinterpret_cast<__half2*>(&v.x));
            float2 q1 = __half22float2(*reinterpret_cast<__half2*>(&v.y));
            a0.x += q0.x; a0.y += q0.y; a0.z += q1.x; a0.w += q1.y;
        }
        a0.x += a1.x + a2.x + a3.x;
        a0.y += a1.y + a2.y + a3.y;
        a0.z += a1.z + a2.z + a3.z;
        a0.w += a1.w + a2.w + a3.w;
        reinterpret_cast<float4*>(g_agg1)[(size_t)wid * 32 + lane] = a0;
    } else {
        const uint32_t* sp = reinterpret_cast<const uint32_t*>(g_s2);  // half2 per elem
        uint32_t sv = sp[(size_t)wid * 32 + lane];
        float2 a0 = __half22float2(*reinterpret_cast<__half2*>(&sv));  // self loop
        float2 a1 = make_float2(0.f, 0.f);
        float2 a2 = make_float2(0.f, 0.f);
        float2 a3 = make_float2(0.f, 0.f);
        int j = beg;
        for (; j + 4 <= end; j += 4) {
            int u0 = g_csr[j], u1 = g_csr[j + 1], u2 = g_csr[j + 2], u3 = g_csr[j + 3];
            uint32_t v0 = sp[(size_t)u0 * 32 + lane];
            uint32_t v1 = sp[(size_t)u1 * 32 + lane];
            uint32_t v2 = sp[(size_t)u2 * 32 + lane];
            uint32_t v3 = sp[(size_t)u3 * 32 + lane];
            float2 q;
            q = __half22float2(*reinterpret_cast<__half2*>(&v0)); a0.x += q.x; a0.y += q.y;
            q = __half22float2(*reinterpret_cast<__half2*>(&v1)); a1.x += q.x; a1.y += q.y;
            q = __half22float2(*reinterpret_cast<__half2*>(&v2)); a2.x += q.x; a2.y += q.y;
            q = __half22float2(*reinterpret_cast<__half2*>(&v3)); a3.x += q.x; a3.y += q.y;
        }
        for (; j < end; j++) {
            uint32_t v = sp[(size_t)g_csr[j] * 32 + lane];
            float2 q = __half22float2(*reinterpret_cast<__half2*>(&v));
            a0.x += q.x; a0.y += q.y;
        }
        a0.x += a1.x + a2.x + a3.x;
        a0.y += a1.y + a2.y + a3.y;
        float di = g_dinv[wid];
        float2 r;
        r.x = di * a0.x + b2[lane * 2 + 0];
        r.y = di * a0.y + b2[lane * 2 + 1];
        reinterpret_cast<float2*>(out)[(size_t)wid * 32 + lane] = r;
    }
}

// -----------------------------------------------------------------------------
extern "C" void kernel_launch(void* const* d_in, const int* in_sizes, int n_in,
                              void* d_out, int out_size)
{
    const float* x  = (const float*)d_in[0];
    const int*   ew = (const int*)d_in[1];
    const float* W1 = (const float*)d_in[2];
    const float* b1 = (const float*)d_in[3];
    const float* W2 = (const float*)d_in[4];
    const float* b2 = (const float*)d_in[5];

    const int n = in_sizes[0] / HID;   // 100000
    const int E = in_sizes[1] / 2;     // 1600000
    const int nblk_scan = (n + SCAN_BLK - 1) / SCAN_BLK;

    const int smem1 = (2 * 128 * KP + 2 * HID * KP) * 2;   // 139264 B
    const int smem2 = (2 * 128 * KP + 2 * ODIM * KP) * 2;  // 104448 B
    cudaFuncSetAttribute(k_tgemm<HID, 1>, cudaFuncAttributeMaxDynamicSharedMemorySize, smem1);
    cudaFuncSetAttribute(k_tgemm<ODIM, 2>, cudaFuncAttributeMaxDynamicSharedMemorySize, smem2);

    k_detect<<<1, 256>>>(ew);

    // CSR build + dinv
    k_zero<<<(n + 255) / 256, 256>>>(n);
    k_count<<<(E + 255) / 256, 256>>>(ew, E);
    k_scan1<<<nblk_scan, SCAN_BLK>>>(n);
    k_scan2<<<1, 1024>>>(nblk_scan);
    k_scan3<<<(n + 255) / 256, 256>>>(n, E);
    k_fill<<<(E + 255) / 256, 256>>>(ew, E);

    k_convw<<<(HID * HID + 255) / 256, 256>>>(W1, W2);

    const int gblk = (n + 127) / 128;
    // layer 1
    k_tgemm<HID, 1><<<gblk, 256, smem1>>>(x, nullptr, n);
    k_gather<1><<<(n + 7) / 8, 256>>>(nullptr, nullptr, n);

    // layer 2 (bias = b1 fused into A staging; epilogue fused into gather)
    k_tgemm<ODIM, 2><<<gblk, 256, smem2>>>(nullptr, b1, n);
    k_gather<2><<<(n + 7) / 8, 256>>>(b2, (float*)d_out, n);
}

// round 8
// speedup vs baseline: 3.9362x; 1.3235x over previous
#include <cuda_runtime.h>
#include <cuda_bf16.h>
#include <cuda_fp16.h>
#include <cstddef>
#include <cstdint>

// ---------------------------------------------------------------------------
// 2-layer GCN. Per layer:  s = dinv * (A @ W);  agg[d] = s[d] + sum s[u];
//                          h = dinv * agg + b
// GEMMs: mma.sync bf16 hi/lo split (3 MMAs, ~fp32 precision), K chunked in 64s
// to halve smem (3-4 blocks/SM). Messages and agg1 stored fp16 (fp32 accum).
// Edge phase: dst-CSR gather, built once per launch.
// ---------------------------------------------------------------------------

#define NMAX 100000
#define EMAX 1700000
#define HID 128
#define ODIM 64
#define SCAN_BLK 512
#define KP 72   // padded K-chunk stride in halfs (conflict-free frag LDS)

__device__ float  g_dinv[NMAX];
__device__ __align__(16) __half g_s1[(size_t)NMAX * HID];     // fp16 messages, layer 1
__device__ __align__(16) __half g_agg1h[(size_t)NMAX * HID];  // fp16 aggregate
__device__ __align__(16) __half g_s2[(size_t)NMAX * ODIM];    // fp16 messages, layer 2
__device__ int    g_is64;

__device__ int g_cnt[NMAX];
__device__ int g_rowptr[NMAX + 1];
__device__ int g_cursor[NMAX];
__device__ int g_csr[EMAX];
__device__ int g_bsum[1024];

__device__ __align__(16) __nv_bfloat16 g_w1t_hi[HID * HID], g_w1t_lo[HID * HID];   // [n][k]
__device__ __align__(16) __nv_bfloat16 g_w2t_hi[ODIM * HID], g_w2t_lo[ODIM * HID]; // [n][k]

// ---- fused pre-pass: dtype detect + cnt zero + W conversion -----------------
__global__ void k_pre(const int* __restrict__ ew,
                      const float* __restrict__ W1, const float* __restrict__ W2, int n)
{
    int i = blockIdx.x * blockDim.x + threadIdx.x;

    if (blockIdx.x == 0) {
        __shared__ int any;
        if (threadIdx.x == 0) any = 0;
        __syncthreads();
        for (int j = threadIdx.x; j < 2048; j += blockDim.x)
            if (ew[2 * j + 1] != 0) any = 1;
        __syncthreads();
        if (threadIdx.x == 0) g_is64 = (any == 0) ? 1 : 0;
    }

    if (i < n) g_cnt[i] = 0;

    if (i < HID * HID) {
        int nn = i >> 7, k = i & 127;
        float v = W1[k * HID + nn];
        __nv_bfloat16 h = __float2bfloat16(v);
        g_w1t_hi[i] = h;
        g_w1t_lo[i] = __float2bfloat16(v - __bfloat162float(h));
    }
    if (i < ODIM * HID) {
        int nn = i >> 7, k = i & 127;
        float v = W2[k * ODIM + nn];
        __nv_bfloat16 h = __float2bfloat16(v);
        g_w2t_hi[i] = h;
        g_w2t_lo[i] = __float2bfloat16(v - __bfloat162float(h));
    }
}

__device__ __forceinline__ int edge_at(const int* __restrict__ w, int i, int is64) {
    return is64 ? w[2 * (size_t)i] : w[i];
}

// ---- CSR build --------------------------------------------------------------
__global__ void k_count(const int* __restrict__ w, int E) {
    int is64 = g_is64;
    const int* dst = w + (size_t)E * (1 + is64);
    int i = blockIdx.x * blockDim.x + threadIdx.x;
    if (i < E) atomicAdd(&g_cnt[edge_at(dst, i, is64)], 1);
}

__global__ void k_scan1(int n) {
    __shared__ int sh[SCAN_BLK];
    int i = blockIdx.x * SCAN_BLK + threadIdx.x;
    int v = (i < n) ? g_cnt[i] : 0;
    sh[threadIdx.x] = v;
    __syncthreads();
    for (int off = 1; off < SCAN_BLK; off <<= 1) {
        int t = (threadIdx.x >= off) ? sh[threadIdx.x - off] : 0;
        __syncthreads();
        sh[threadIdx.x] += t;
        __syncthreads();
    }
    if (i < n) g_rowptr[i] = sh[threadIdx.x] - v;
    if (threadIdx.x == SCAN_BLK - 1) g_bsum[blockIdx.x] = sh[SCAN_BLK - 1];
}

__global__ void k_scan2(int nblk) {
    __shared__ int sh[1024];
    int v = (threadIdx.x < nblk) ? g_bsum[threadIdx.x] : 0;
    sh[threadIdx.x] = v;
    __syncthreads();
    for (int off = 1; off < 1024; off <<= 1) {
        int t = (threadIdx.x >= off) ? sh[threadIdx.x - off] : 0;
        __syncthreads();
        sh[threadIdx.x] += t;
        __syncthreads();
    }
    if (threadIdx.x < nblk) g_bsum[threadIdx.x] = sh[threadIdx.x] - v;
}

__global__ void k_scan3(int n, int E) {
    int i = blockIdx.x * blockDim.x + threadIdx.x;
    if (i < n) {
        int rp = g_rowptr[i] + g_bsum[i / SCAN_BLK];
        g_rowptr[i] = rp;
        g_cursor[i] = rp;
        g_dinv[i]   = rsqrtf((float)g_cnt[i] + 1.0f);
        if (i == n - 1) g_rowptr[n] = E;
    }
}

__global__ void k_fill(const int* __restrict__ w, int E) {
    int is64 = g_is64;
    const int* src = w;
    const int* dst = w + (size_t)E * (1 + is64);
    int i = blockIdx.x * blockDim.x + threadIdx.x;
    if (i < E) {
        int u = edge_at(src, i, is64);
        int v = edge_at(dst, i, is64);
        int pos = atomicAdd(&g_cursor[v], 1);
        g_csr[pos] = u;
    }
}

// ---- tensor-core GEMM ---------------------------------------------------------
__device__ __forceinline__ void mma16816(float c[4], const uint32_t a[4], const uint32_t b[2]) {
    asm volatile(
        "mma.sync.aligned.m16n8k16.row.col.f32.bf16.bf16.f32 "
        "{%0,%1,%2,%3}, {%4,%5,%6,%7}, {%8,%9}, {%0,%1,%2,%3};\n"
        : "+f"(c[0]), "+f"(c[1]), "+f"(c[2]), "+f"(c[3])
        : "r"(a[0]), "r"(a[1]), "r"(a[2]), "r"(a[3]), "r"(b[0]), "r"(b[1]));
}

__device__ __forceinline__ uint32_t pack_bf2(__nv_bfloat16 a, __nv_bfloat16 b) {
    return (uint32_t)__bfloat16_as_ushort(a) | ((uint32_t)__bfloat16_as_ushort(b) << 16);
}

// Block: 128 rows x NOUT cols, 256 threads (8 warps, each m16 x NOUT).
// K processed in two 64-chunks (smem halved vs monolithic).
// LAYER==1: A = x (fp32).  LAYER==2: A = g_agg1h (fp16), dinv*v + b1 fused on load.
// Epilogue: s_out(fp16) = dinv[row] * acc.
template <int NOUT, int LAYER>
__global__ void __launch_bounds__(256) k_tgemm(
    const float* __restrict__ A_in, const float* __restrict__ bias, int n)
{
    constexpr int NT = NOUT / 8;
    extern __shared__ __nv_bfloat16 sm[];
    __nv_bfloat16* Ahi = sm;                    // [128][KP]
    __nv_bfloat16* Alo = Ahi + 128 * KP;
    __nv_bfloat16* Bhi = Alo + 128 * KP;        // [NOUT][KP]
    __nv_bfloat16* Blo = Bhi + NOUT * KP;

    __half* s_out = (LAYER == 1) ? g_s1 : g_s2;
    const __nv_bfloat16* Wh = (LAYER == 1) ? g_w1t_hi : g_w2t_hi;
    const __nv_bfloat16* Wl = (LAYER == 1) ? g_w1t_lo : g_w2t_lo;

    const int tid  = threadIdx.x;
    const int row0 = blockIdx.x * 128;
    const int w = tid >> 5, lane = tid & 31;
    const int g = lane >> 2, tq = lane & 3;
    const int mrow = w * 16;

    float acc[NT][4];
#pragma unroll
    for (int nt = 0; nt < NT; nt++)
#pragma unroll
        for (int j = 0; j < 4; j++) acc[nt][j] = 0.0f;

#pragma unroll
    for (int kk = 0; kk < 128; kk += 64) {
        if (kk) __syncthreads();

        // stage A chunk (-> bf16 hi/lo), fused layer-2 input transform
        for (int base = tid * 4; base < 128 * 64; base += 256 * 4) {
            int r = base >> 6, k = base & 63;
            int row = row0 + r;
            float4 v = make_float4(0.f, 0.f, 0.f, 0.f);
            if (row < n) {
                if (LAYER == 1) {
                    v = *reinterpret_cast<const float4*>(&A_in[(size_t)row * 128 + kk + k]);
                } else {
                    uint2 hv = *reinterpret_cast<const uint2*>(&g_agg1h[(size_t)row * 128 + kk + k]);
                    float2 p0 = __half22float2(*reinterpret_cast<__half2*>(&hv.x));
                    float2 p1 = __half22float2(*reinterpret_cast<__half2*>(&hv.y));
                    float d = g_dinv[row];
                    float4 bb = *reinterpret_cast<const float4*>(&bias[kk + k]);
                    v.x = fmaf(d, p0.x, bb.x); v.y = fmaf(d, p0.y, bb.y);
                    v.z = fmaf(d, p1.x, bb.z); v.w = fmaf(d, p1.y, bb.w);
                }
            }
            __nv_bfloat16 h0 = __float2bfloat16(v.x), h1 = __float2bfloat16(v.y);
            __nv_bfloat16 h2 = __float2bfloat16(v.z), h3 = __float2bfloat16(v.w);
            __nv_bfloat16 l0 = __float2bfloat16(v.x - __bfloat162float(h0));
            __nv_bfloat16 l1 = __float2bfloat16(v.y - __bfloat162float(h1));
            __nv_bfloat16 l2 = __float2bfloat16(v.z - __bfloat162float(h2));
            __nv_bfloat16 l3 = __float2bfloat16(v.w - __bfloat162float(h3));
            *reinterpret_cast<uint2*>(&Ahi[r * KP + k]) = make_uint2(pack_bf2(h0, h1), pack_bf2(h2, h3));
            *reinterpret_cast<uint2*>(&Alo[r * KP + k]) = make_uint2(pack_bf2(l0, l1), pack_bf2(l2, l3));
        }
        // stage B chunk (bf16 hi/lo, transposed [n][k])
        for (int base = tid * 8; base < NOUT * 64; base += 256 * 8) {
            int nn = base >> 6, k = base & 63;
            *reinterpret_cast<uint4*>(&Bhi[nn * KP + k]) =
                *reinterpret_cast<const uint4*>(&Wh[nn * 128 + kk + k]);
            *reinterpret_cast<uint4*>(&Blo[nn * KP + k]) =
                *reinterpret_cast<const uint4*>(&Wl[nn * 128 + kk + k]);
        }
        __syncthreads();

#pragma unroll
        for (int kt = 0; kt < 4; kt++) {
            const int k0 = kt * 16;
            uint32_t ah[4], al[4];
            const int ra = (mrow + g) * KP + k0 + tq * 2;
            const int rb = (mrow + g + 8) * KP + k0 + tq * 2;
            ah[0] = *reinterpret_cast<const uint32_t*>(&Ahi[ra]);
            ah[1] = *reinterpret_cast<const uint32_t*>(&Ahi[rb]);
            ah[2] = *reinterpret_cast<const uint32_t*>(&Ahi[ra + 8]);
            ah[3] = *reinterpret_cast<const uint32_t*>(&Ahi[rb + 8]);
            al[0] = *reinterpret_cast<const uint32_t*>(&Alo[ra]);
            al[1] = *reinterpret_cast<const uint32_t*>(&Alo[rb]);
            al[2] = *reinterpret_cast<const uint32_t*>(&Alo[ra + 8]);
            al[3] = *reinterpret_cast<const uint32_t*>(&Alo[rb + 8]);
#pragma unroll
            for (int nt = 0; nt < NT; nt++) {
                uint32_t bh[2], bl[2];
                const int rn = (nt * 8 + g) * KP + k0 + tq * 2;
                bh[0] = *reinterpret_cast<const uint32_t*>(&Bhi[rn]);
                bh[1] = *reinterpret_cast<const uint32_t*>(&Bhi[rn + 8]);
                bl[0] = *reinterpret_cast<const uint32_t*>(&Blo[rn]);
                bl[1] = *reinterpret_cast<const uint32_t*>(&Blo[rn + 8]);
                mma16816(acc[nt], ah, bh);
                mma16816(acc[nt], ah, bl);
                mma16816(acc[nt], al, bh);
            }
        }
    }

    const int r0g = row0 + mrow + g;
    const int r1g = r0g + 8;
    const float d0 = (r0g < n) ? g_dinv[r0g] : 0.f;
    const float d1 = (r1g < n) ? g_dinv[r1g] : 0.f;
#pragma unroll
    for (int nt = 0; nt < NT; nt++) {
        if (r0g < n) {
            __half2 o = __floats2half2_rn(d0 * acc[nt][0], d0 * acc[nt][1]);
            *reinterpret_cast<__half2*>(&s_out[(size_t)r0g * NOUT + nt * 8 + tq * 2]) = o;
        }
        if (r1g < n) {
            __half2 o = __floats2half2_rn(d1 * acc[nt][2], d1 * acc[nt][3]);
            *reinterpret_cast<__half2*>(&s_out[(size_t)r1g * NOUT + nt * 8 + tq * 2]) = o;
        }
    }
}

// ---- CSR gather: one warp per destination row ---------------------------------
// fp16 messages, fp32 accumulation.
// LAYER==1: lane owns 4 feats; writes fp16 agg1.
// LAYER==2: lane owns 2 feats; fused epilogue -> d_out fp32.
template <int LAYER>
__global__ void k_gather(const float* __restrict__ b2, float* __restrict__ out, int n)
{
    const int lane = threadIdx.x & 31;
    const int wid  = (blockIdx.x * blockDim.x + threadIdx.x) >> 5;
    if (wid >= n) return;

    const int beg = g_rowptr[wid];
    const int end = g_rowptr[wid + 1];

    if (LAYER == 1) {
        const uint2* sp = reinterpret_cast<const uint2*>(g_s1);  // 4 halfs per elem
        uint2 sv = sp[(size_t)wid * 32 + lane];                  // self loop
        float2 p0 = __half22float2(*reinterpret_cast<__half2*>(&sv.x));
        float2 p1 = __half22float2(*reinterpret_cast<__half2*>(&sv.y));
        float4 a0 = make_float4(p0.x, p0.y, p1.x, p1.y);
        float4 a1 = make_float4(0.f, 0.f, 0.f, 0.f);
        float4 a2 = make_float4(0.f, 0.f, 0.f, 0.f);
        float4 a3 = make_float4(0.f, 0.f, 0.f, 0.f);
        int j = beg;
        for (; j + 4 <= end; j += 4) {
            int u0 = g_csr[j], u1 = g_csr[j + 1], u2 = g_csr[j + 2], u3 = g_csr[j + 3];
            uint2 v0 = sp[(size_t)u0 * 32 + lane];
            uint2 v1 = sp[(size_t)u1 * 32 + lane];
            uint2 v2 = sp[(size_t)u2 * 32 + lane];
            uint2 v3 = sp[(size_t)u3 * 32 + lane];
            float2 q0, q1;
            q0 = __half22float2(*reinterpret_cast<__half2*>(&v0.x));
            q1 = __half22float2(*reinterpret_cast<__half2*>(&v0.y));
            a0.x += q0.x; a0.y += q0.y; a0.z += q1.x; a0.w += q1.y;
            q0 = __half22float2(*reinterpret_cast<__half2*>(&v1.x));
            q1 = __half22float2(*reinterpret_cast<__half2*>(&v1.y));
            a1.x += q0.x; a1.y += q0.y; a1.z += q1.x; a1.w += q1.y;
            q0 = __half22float2(*reinterpret_cast<__half2*>(&v2.x));
            q1 = __half22float2(*reinterpret_cast<__half2*>(&v2.y));
            a2.x += q0.x; a2.y += q0.y; a2.z += q1.x; a2.w += q1.y;
            q0 = __half22float2(*reinterpret_cast<__half2*>(&v3.x));
            q1 = __half22float2(*reinterpret_cast<__half2*>(&v3.y));
            a3.x += q0.x; a3.y += q0.y; a3.z += q1.x; a3.w += q1.y;
        }
        for (; j < end; j++) {
            uint2 v = sp[(size_t)g_csr[j] * 32 + lane];
            float2 q0 = __half22float2(*reinterpret_cast<__half2*>(&v.x));
            float2 q1 = __half22float2(*reinterpret_cast<__half2*>(&v.y));
            a0.x += q0.x; a0.y += q0.y; a0.z += q1.x; a0.w += q1.y;
        }
        a0.x += a1.x + a2.x + a3.x;
        a0.y += a1.y + a2.y + a3.y;
        a0.z += a1.z + a2.z + a3.z;
        a0.w += a1.w + a2.w + a3.w;
        __half2 o0 = __floats2half2_rn(a0.x, a0.y);
        __half2 o1 = __floats2half2_rn(a0.z, a0.w);
        uint2 ov = make_uint2(*reinterpret_cast<uint32_t*>(&o0), *reinterpret_cast<uint32_t*>(&o1));
        reinterpret_cast<uint2*>(g_agg1h)[(size_t)wid * 32 + lane] = ov;
    } else {
        const uint32_t* sp = reinterpret_cast<const uint32_t*>(g_s2);  // half2 per elem
        uint32_t sv = sp[(size_t)wid * 32 + lane];
        float2 a0 = __half22float2(*reinterpret_cast<__half2*>(&sv));  // self loop
        float2 a1 = make_float2(0.f, 0.f);
        float2 a2 = make_float2(0.f, 0.f);
        float2 a3 = make_float2(0.f, 0.f);
        int j = beg;
        for (; j + 4 <= end; j += 4) {
            int u0 = g_csr[j], u1 = g_csr[j + 1], u2 = g_csr[j + 2], u3 = g_csr[j + 3];
            uint32_t v0 = sp[(size_t)u0 * 32 + lane];
            uint32_t v1 = sp[(size_t)u1 * 32 + lane];
            uint32_t v2 = sp[(size_t)u2 * 32 + lane];
            uint32_t v3 = sp[(size_t)u3 * 32 + lane];
            float2 q;
            q = __half22float2(*reinterpret_cast<__half2*>(&v0)); a0.x += q.x; a0.y += q.y;
            q = __half22float2(*reinterpret_cast<__half2*>(&v1)); a1.x += q.x; a1.y += q.y;
            q = __half22float2(*reinterpret_cast<__half2*>(&v2)); a2.x += q.x; a2.y += q.y;
            q = __half22float2(*reinterpret_cast<__half2*>(&v3)); a3.x += q.x; a3.y += q.y;
        }
        for (; j < end; j++) {
            uint32_t v = sp[(size_t)g_csr[j] * 32 + lane];
            float2 q = __half22float2(*reinterpret_cast<__half2*>(&v));
            a0.x += q.x; a0.y += q.y;
        }
        a0.x += a1.x + a2.x + a3.x;
        a0.y += a1.y + a2.y + a3.y;
        float di = g_dinv[wid];
        float2 r;
        r.x = di * a0.x + b2[lane * 2 + 0];
        r.y = di * a0.y + b2[lane * 2 + 1];
        reinterpret_cast<float2*>(out)[(size_t)wid * 32 + lane] = r;
    }
}

// -----------------------------------------------------------------------------
extern "C" void kernel_launch(void* const* d_in, const int* in_sizes, int n_in,
                              void* d_out, int out_size)
{
    const float* x  = (const float*)d_in[0];
    const int*   ew = (const int*)d_in[1];
    const float* W1 = (const float*)d_in[2];
    const float* b1 = (const float*)d_in[3];
    const float* W2 = (const float*)d_in[4];
    const float* b2 = (const float*)d_in[5];

    const int n = in_sizes[0] / HID;   // 100000
    const int E = in_sizes[1] / 2;     // 1600000
    const int nblk_scan = (n + SCAN_BLK - 1) / SCAN_BLK;

    const int smem1 = (2 * 128 * KP + 2 * HID * KP) * 2;   // 73728 B
    const int smem2 = (2 * 128 * KP + 2 * ODIM * KP) * 2;  // 55296 B
    cudaFuncSetAttribute(k_tgemm<HID, 1>, cudaFuncAttributeMaxDynamicSharedMemorySize, smem1);
    cudaFuncSetAttribute(k_tgemm<ODIM, 2>, cudaFuncAttributeMaxDynamicSharedMemorySize, smem2);

    // fused pre-pass (detect + zero + W conv)
    k_pre<<<(n + 255) / 256, 256>>>(ew, W1, W2, n);

    // CSR build + dinv
    k_count<<<(E + 255) / 256, 256>>>(ew, E);
    k_scan1<<<nblk_scan, SCAN_BLK>>>(n);
    k_scan2<<<1, 1024>>>(nblk_scan);
    k_scan3<<<(n + 255) / 256, 256>>>(n, E);
    k_fill<<<(E + 255) / 256, 256>>>(ew, E);

    const int gblk = (n + 127) / 128;
    // layer 1
    k_tgemm<HID, 1><<<gblk, 256, smem1>>>(x, nullptr, n);
    k_gather<1><<<(n + 7) / 8, 256>>>(nullptr, nullptr, n);

    // layer 2 (bias = b1 fused into A staging; epilogue fused into gather)
    k_tgemm<ODIM, 2><<<gblk, 256, smem2>>>(nullptr, b1, n);
    k_gather<2><<<(n + 7) / 8, 256>>>(b2, (float*)d_out, n);
}